// round 2
// baseline (speedup 1.0000x reference)
#include <cuda_runtime.h>
#include <cuda_bf16.h>
#include <cstdint>

// Problem dims (fixed by the reference)
#define BB 16
#define TT 128
#define HH 512
#define VV 32000
#define G4 2048   // 4*H

// ---------------- device scratch (static: no allocation allowed) -----------
__device__ float    g_X [TT*BB*HH];   // gathered embeddings, row = t*16+b
__device__ float    g_Xg[TT*BB*G4];   // x@W_ih^T + b_ih + b_hh
__device__ float    g_Hs[TT*BB*HH];   // hidden states, row = t*16+b
__device__ float    g_bias[G4];       // b_ih + b_hh
__device__ unsigned g_bar[TT];        // per-step grid barrier counters

// ---------------- small helpers -------------------------------------------
__device__ __forceinline__ float sigm(float x) { return 1.0f / (1.0f + expf(-x)); }

__device__ __forceinline__ void ldsm4(uint32_t* r, uint32_t addr) {
    asm volatile("ldmatrix.sync.aligned.m8n8.x4.shared.b16 {%0,%1,%2,%3}, [%4];"
                 : "=r"(r[0]), "=r"(r[1]), "=r"(r[2]), "=r"(r[3]) : "r"(addr));
}
__device__ __forceinline__ void ldsm2(uint32_t* r, uint32_t addr) {
    asm volatile("ldmatrix.sync.aligned.m8n8.x2.shared.b16 {%0,%1}, [%2];"
                 : "=r"(r[0]), "=r"(r[1]) : "r"(addr));
}
__device__ __forceinline__ void mma16816(float* c, const uint32_t* a, const uint32_t* b) {
    asm volatile("mma.sync.aligned.m16n8k16.row.col.f32.bf16.bf16.f32 "
                 "{%0,%1,%2,%3}, {%4,%5,%6,%7}, {%8,%9}, {%0,%1,%2,%3};"
                 : "+f"(c[0]), "+f"(c[1]), "+f"(c[2]), "+f"(c[3])
                 : "r"(a[0]), "r"(a[1]), "r"(a[2]), "r"(a[3]), "r"(b[0]), "r"(b[1]));
}

// ---------------- kernel 1: embedding gather ------------------------------
// g_X[t*16+b][e] = emb[xs[b][t]][e]
__global__ void k_gather(const int* __restrict__ xs, const float* __restrict__ emb) {
    int f = blockIdx.x * 256 + threadIdx.x;          // float4 id, 2048*128 total
    int row = f >> 7;
    int e   = (f & 127) << 2;
    int t = row >> 4, b = row & 15;
    int tok = xs[b * TT + t];
    *(float4*)&g_X[row * HH + e] = *(const float4*)&emb[(size_t)tok * HH + e];
}

// ---------------- kernel 2: bias sum + barrier reset ----------------------
__global__ void k_prep(const float* __restrict__ b_ih, const float* __restrict__ b_hh) {
    int i = blockIdx.x * 256 + threadIdx.x;
    if (i < G4) g_bias[i] = b_ih[i] + b_hh[i];
    if (i < TT) g_bar[i] = 0u;
}

// ---------------- kernel 3: bf16x3 split GEMM -----------------------------
// C[n][m] = dot(A[n,:], Bt[m,:]) + bias[m];  A:[N,K] f32, Bt:[M,K] f32.
// Computed as a_hi*b_hi + a_hi*b_lo + a_lo*b_hi (bf16 mma, fp32 accum).
// Requires N%128==0, M%128==0, K%32==0 (true for both uses).
__global__ void __launch_bounds__(256) gemm_bf16x3(
    const float* __restrict__ A, const float* __restrict__ Bt,
    const float* __restrict__ bias, float* __restrict__ C,
    int M, int K)
{
    const int tid  = threadIdx.x;
    const int lane = tid & 31, wid = tid >> 5;
    const int warp_n = wid >> 2;          // 0..1 -> 64-row slab (N dim of C)
    const int warp_m = wid & 3;           // 0..3 -> 32-col slab (M dim of C)
    const int n0 = blockIdx.y * 128;
    const int m0 = blockIdx.x * 128;

    // smem tiles: 128 rows x 32 k, stride 40 bf16 (80B rows, conflict-free ldmatrix)
    __shared__ __nv_bfloat16 sAh[128 * 40], sAl[128 * 40];
    __shared__ __nv_bfloat16 sBh[128 * 40], sBl[128 * 40];

    float c[4][4][4];
#pragma unroll
    for (int i = 0; i < 4; i++)
#pragma unroll
        for (int j = 0; j < 4; j++)
#pragma unroll
            for (int q = 0; q < 4; q++) c[i][j][q] = 0.0f;

    const uint32_t uAh = (uint32_t)__cvta_generic_to_shared(sAh);
    const uint32_t uAl = (uint32_t)__cvta_generic_to_shared(sAl);
    const uint32_t uBh = (uint32_t)__cvta_generic_to_shared(sBh);
    const uint32_t uBl = (uint32_t)__cvta_generic_to_shared(sBl);

    // per-lane ldmatrix source coordinates
    const int a_lr = lane & 7, a_sel = lane >> 3;
    const int a_row = (a_sel & 1) * 8 + a_lr;     // within 16-row tile
    const int a_col = (a_sel >> 1) * 8;           // 0 or 8
    const int b_l   = lane & 15;
    const int b_row = b_l & 7;                    // within 8-row tile
    const int b_col = (b_l >> 3) * 8;             // 0 or 8

    for (int kc = 0; kc < K; kc += 32) {
        // ---- load + split f32 -> bf16 hi/lo ----
#pragma unroll
        for (int i = 0; i < 4; i++) {
            int f   = tid + i * 256;              // 0..1023 float4 slots
            int row = f >> 3;
            int k4  = (f & 7) << 2;
            float4 va = *(const float4*)&A [(size_t)(n0 + row) * K + kc + k4];
            float4 vb = *(const float4*)&Bt[(size_t)(m0 + row) * K + kc + k4];
            float xa[4] = {va.x, va.y, va.z, va.w};
            float xb[4] = {vb.x, vb.y, vb.z, vb.w};
            int o = row * 40 + k4;
#pragma unroll
            for (int q = 0; q < 4; q++) {
                __nv_bfloat16 h = __float2bfloat16(xa[q]);
                sAh[o + q] = h;
                sAl[o + q] = __float2bfloat16(xa[q] - __bfloat162float(h));
                __nv_bfloat16 g = __float2bfloat16(xb[q]);
                sBh[o + q] = g;
                sBl[o + q] = __float2bfloat16(xb[q] - __bfloat162float(g));
            }
        }
        __syncthreads();

#pragma unroll
        for (int kk = 0; kk < 32; kk += 16) {
            uint32_t ah[4][4], al[4][4], bh[4][2], bl[4][2];
#pragma unroll
            for (int i = 0; i < 4; i++) {
                int r = warp_n * 64 + i * 16 + a_row;
                uint32_t off = (uint32_t)((r * 40 + kk + a_col) * 2);
                ldsm4(ah[i], uAh + off);
                ldsm4(al[i], uAl + off);
            }
#pragma unroll
            for (int j = 0; j < 4; j++) {
                int r = warp_m * 32 + j * 8 + b_row;
                uint32_t off = (uint32_t)((r * 40 + kk + b_col) * 2);
                ldsm2(bh[j], uBh + off);
                ldsm2(bl[j], uBl + off);
            }
#pragma unroll
            for (int i = 0; i < 4; i++)
#pragma unroll
                for (int j = 0; j < 4; j++) {
                    mma16816(c[i][j], ah[i], bh[j]);
                    mma16816(c[i][j], ah[i], bl[j]);
                    mma16816(c[i][j], al[i], bh[j]);
                }
        }
        __syncthreads();
    }

    // ---- epilogue: add bias, store f32 ----
#pragma unroll
    for (int i = 0; i < 4; i++) {
        int n = n0 + warp_n * 64 + i * 16 + (lane >> 2);
#pragma unroll
        for (int j = 0; j < 4; j++) {
            int m = m0 + warp_m * 32 + j * 8 + ((lane & 3) << 1);
            float bx = bias[m], by = bias[m + 1];
            *(float2*)&C[(size_t)n * M + m]       = make_float2(c[i][j][0] + bx, c[i][j][1] + by);
            *(float2*)&C[(size_t)(n + 8) * M + m] = make_float2(c[i][j][2] + bx, c[i][j][3] + by);
        }
    }
}

// ---------------- kernel 4: persistent LSTM -------------------------------
// 128 CTAs x 128 threads. CTA cb owns h-indices j in [cb*4, cb*4+4), i.e.
// 16 gate rows (4 gates x 4 j). W_hh slice lives in SMEM for the whole kernel.
// Per step: broadcast h_prev into SMEM, each thread computes 2 gate dots,
// 64 threads apply activations + cell update, grid barrier, repeat.
// 128 CTAs <= 148 SMs and smem fits -> whole grid is co-resident (no deadlock).
__global__ void __launch_bounds__(128) k_lstm(const float* __restrict__ enc_h,
                                              const float* __restrict__ enc_c,
                                              const float* __restrict__ W_hh) {
    extern __shared__ float sm[];
    float* w_sh    = sm;                 // [16][516]
    float* h_sh    = sm + 16 * 516;      // [16][516]  (b-major)
    float* c_sh    = sm + 32 * 516;      // [4][16]    (jj, b)
    float* gate_sh = c_sh + 64;          // [16][16]   (rl = gate*4+jj, b)

    const int cb  = blockIdx.x;
    const int tid = threadIdx.x;

    // load W_hh slice (rl -> global row gate*512 + cb*4 + jj)
    for (int f = tid; f < 2048; f += 128) {
        int rl = f >> 7, k4 = (f & 127) << 2;
        int grow = (rl >> 2) * HH + cb * 4 + (rl & 3);
        *(float4*)&w_sh[rl * 516 + k4] = *(const float4*)&W_hh[(size_t)grow * HH + k4];
    }
    if (tid < 64) {
        int jj = tid >> 4, b = tid & 15;
        c_sh[jj * 16 + b] = enc_c[b * HH + cb * 4 + jj];
    }
    __syncthreads();

    const int rp = tid >> 4;             // 0..7 -> rows 2rp, 2rp+1
    const int b  = tid & 15;
    const int r0 = rp * 2, r1 = r0 + 1;
    const int g0 = r0 >> 2, j0 = r0 & 3;
    const int g1 = r1 >> 2, j1 = r1 & 3;

    for (int t = 0; t < TT; t++) {
        const float* hsrc = (t == 0) ? enc_h : &g_Hs[(size_t)(t - 1) * BB * HH];
        for (int f = tid; f < 2048; f += 128) {
            int bb = f >> 7, k4 = (f & 127) << 2;
            *(float4*)&h_sh[bb * 516 + k4] = *(const float4*)&hsrc[bb * HH + k4];
        }
        __syncthreads();

        float acc0 = g_Xg[(size_t)(t * BB + b) * G4 + g0 * HH + cb * 4 + j0];
        float acc1 = g_Xg[(size_t)(t * BB + b) * G4 + g1 * HH + cb * 4 + j1];
        const float* hp = &h_sh[b * 516];
        const float* w0 = &w_sh[r0 * 516];
        const float* w1 = &w_sh[r1 * 516];
#pragma unroll 8
        for (int k = 0; k < HH; k += 4) {
            float4 hv = *(const float4*)&hp[k];
            float4 wa = *(const float4*)&w0[k];
            float4 wb = *(const float4*)&w1[k];
            acc0 += hv.x * wa.x + hv.y * wa.y + hv.z * wa.z + hv.w * wa.w;
            acc1 += hv.x * wb.x + hv.y * wb.y + hv.z * wb.z + hv.w * wb.w;
        }
        gate_sh[r0 * 16 + b] = acc0;
        gate_sh[r1 * 16 + b] = acc1;
        __syncthreads();

        if (tid < 64) {
            int jj = tid >> 4, bb = tid & 15;
            float iv = sigm (gate_sh[(0 * 4 + jj) * 16 + bb]);
            float fv = sigm (gate_sh[(1 * 4 + jj) * 16 + bb]);
            float gv = tanhf(gate_sh[(2 * 4 + jj) * 16 + bb]);
            float ov = sigm (gate_sh[(3 * 4 + jj) * 16 + bb]);
            float cc = fv * c_sh[jj * 16 + bb] + iv * gv;
            c_sh[jj * 16 + bb] = cc;
            g_Hs[(size_t)(t * BB + bb) * HH + cb * 4 + jj] = ov * tanhf(cc);
        }
        // ---- grid barrier (release: fence+sync before arrive; acquire after spin)
        __threadfence();
        __syncthreads();
        if (tid == 0) {
            atomicAdd(&g_bar[t], 1u);
            while (((volatile unsigned*)g_bar)[t] < (unsigned)gridDim.x) __nanosleep(64);
            __threadfence();
        }
        __syncthreads();
    }
}

// ---------------- launcher -------------------------------------------------
extern "C" void kernel_launch(void* const* d_in, const int* in_sizes, int n_in,
                              void* d_out, int out_size) {
    const int*   xs    = (const int*)  d_in[0];
    // d_in[1] = xs_len (unused by reference semantics)
    const float* enc_h = (const float*)d_in[2];
    const float* enc_c = (const float*)d_in[3];
    const float* emb   = (const float*)d_in[4];
    const float* W_ih  = (const float*)d_in[5];
    const float* W_hh  = (const float*)d_in[6];
    const float* b_ih  = (const float*)d_in[7];
    const float* b_hh  = (const float*)d_in[8];
    const float* W_out = (const float*)d_in[9];
    const float* b_out = (const float*)d_in[10];
    float* out = (float*)d_out;

    float *pX, *pXg, *pH, *pbias;
    cudaGetSymbolAddress((void**)&pX,    g_X);
    cudaGetSymbolAddress((void**)&pXg,   g_Xg);
    cudaGetSymbolAddress((void**)&pH,    g_Hs);
    cudaGetSymbolAddress((void**)&pbias, g_bias);

    k_gather<<<1024, 256>>>(xs, emb);
    k_prep<<<8, 256>>>(b_ih, b_hh);

    // Xg = X @ W_ih^T + (b_ih + b_hh)   [2048 x 2048]
    gemm_bf16x3<<<dim3(G4 / 128, (TT * BB) / 128), 256>>>(pX, W_ih, pbias, pXg, G4, HH);

    int lsmem = (2 * 16 * 516 + 64 + 256) * (int)sizeof(float);  // ~67 KB
    cudaFuncSetAttribute(k_lstm, cudaFuncAttributeMaxDynamicSharedMemorySize, lsmem);
    k_lstm<<<128, 128, lsmem>>>(enc_h, enc_c, W_hh);

    // logits = Hs @ W_out^T + b_out     [2048 x 32000]
    gemm_bf16x3<<<dim3(VV / 128, (TT * BB) / 128), 256>>>(pH, W_out, b_out, out, VV, HH);
}

// round 4
// speedup vs baseline: 1.0981x; 1.0981x over previous
#include <cuda_runtime.h>
#include <cuda_bf16.h>
#include <cstdint>

// Problem dims (fixed by the reference)
#define BB 16
#define TT 128
#define HH 512
#define VV 32000
#define G4 2048   // 4*H

// ---------------- device scratch (static: no allocation allowed) -----------
__device__ __nv_bfloat16 g_Xh   [TT*BB*HH];  // x embeddings, bf16 hi
__device__ __nv_bfloat16 g_Xl   [TT*BB*HH];  // x embeddings, bf16 lo
__device__ __nv_bfloat16 g_Wih_h[G4*HH];
__device__ __nv_bfloat16 g_Wih_l[G4*HH];
__device__ __nv_bfloat16 g_Wout_h[(size_t)VV*HH];
__device__ __nv_bfloat16 g_Wout_l[(size_t)VV*HH];
__device__ __nv_bfloat16 g_Hh   [TT*BB*HH];  // hidden states bf16 hi
__device__ __nv_bfloat16 g_Hl   [TT*BB*HH];  // hidden states bf16 lo
__device__ float    g_Xg[TT*BB*G4];   // x@W_ih^T + b_ih + b_hh (f32)
__device__ float    g_Hs[TT*BB*HH];   // hidden states f32 (for recurrence)
__device__ float    g_bias[G4];       // b_ih + b_hh
__device__ unsigned g_bar[TT];        // per-step grid barrier counters

// ---------------- helpers --------------------------------------------------
__device__ __forceinline__ float sigm(float x) { return 1.0f / (1.0f + expf(-x)); }

__device__ __forceinline__ uint32_t smem_u32(const void* p) {
    uint32_t a;
    asm("{ .reg .u64 t; cvta.to.shared.u64 t, %1; cvt.u32.u64 %0, t; }" : "=r"(a) : "l"(p));
    return a;
}
__device__ __forceinline__ uint32_t sw128(uint32_t b) { return b ^ ((b >> 3) & 0x70); }

__device__ __forceinline__ void cpasync16(uint32_t dst, const void* src) {
    asm volatile("cp.async.cg.shared.global [%0], [%1], 16;" :: "r"(dst), "l"(src) : "memory");
}
__device__ __forceinline__ void cp_commit() { asm volatile("cp.async.commit_group;" ::: "memory"); }
template<int N> __device__ __forceinline__ void cp_wait() {
    asm volatile("cp.async.wait_group %0;" :: "n"(N) : "memory");
}

__device__ __forceinline__ void ldsm4(uint32_t* r, uint32_t addr) {
    asm volatile("ldmatrix.sync.aligned.m8n8.x4.shared.b16 {%0,%1,%2,%3}, [%4];"
                 : "=r"(r[0]), "=r"(r[1]), "=r"(r[2]), "=r"(r[3]) : "r"(addr));
}
__device__ __forceinline__ void ldsm2(uint32_t* r, uint32_t addr) {
    asm volatile("ldmatrix.sync.aligned.m8n8.x2.shared.b16 {%0,%1}, [%2];"
                 : "=r"(r[0]), "=r"(r[1]) : "r"(addr));
}
__device__ __forceinline__ void mma16816(float* c, const uint32_t* a, const uint32_t* b) {
    asm volatile("mma.sync.aligned.m16n8k16.row.col.f32.bf16.bf16.f32 "
                 "{%0,%1,%2,%3}, {%4,%5,%6,%7}, {%8,%9}, {%0,%1,%2,%3};"
                 : "+f"(c[0]), "+f"(c[1]), "+f"(c[2]), "+f"(c[3])
                 : "r"(a[0]), "r"(a[1]), "r"(a[2]), "r"(a[3]), "r"(b[0]), "r"(b[1]));
}

// split one float4 into packed bf16 hi/lo pairs
__device__ __forceinline__ void split4(float4 v, uint2& hi, uint2& lo) {
    float xs[4] = {v.x, v.y, v.z, v.w};
    unsigned h[4], l[4];
#pragma unroll
    for (int q = 0; q < 4; q++) {
        __nv_bfloat16 hb = __float2bfloat16(xs[q]);
        __nv_bfloat16 lb = __float2bfloat16(xs[q] - __bfloat162float(hb));
        h[q] = *(unsigned short*)&hb;
        l[q] = *(unsigned short*)&lb;
    }
    hi.x = h[0] | (h[1] << 16); hi.y = h[2] | (h[3] << 16);
    lo.x = l[0] | (l[1] << 16); lo.y = l[2] | (l[3] << 16);
}

// ---------------- kernel 1: embedding gather + bf16 split -----------------
__global__ void k_gather(const int* __restrict__ xs, const float* __restrict__ emb) {
    int f = blockIdx.x * 256 + threadIdx.x;          // float4 id, 2048*128 total
    int row = f >> 7;
    int e   = (f & 127) << 2;
    int t = row >> 4, b = row & 15;
    int tok = xs[b * TT + t];
    float4 v = *(const float4*)&emb[(size_t)tok * HH + e];
    uint2 hi, lo; split4(v, hi, lo);
    *(uint2*)&g_Xh[row * HH + e] = hi;
    *(uint2*)&g_Xl[row * HH + e] = lo;
}

// ---------------- kernel 2: bias sum + barrier reset ----------------------
__global__ void k_prep(const float* __restrict__ b_ih, const float* __restrict__ b_hh) {
    int i = blockIdx.x * 256 + threadIdx.x;
    if (i < G4) g_bias[i] = b_ih[i] + b_hh[i];
    if (i < TT) g_bar[i] = 0u;
}

// ---------------- kernel 3: weight bf16 hi/lo conversion ------------------
__global__ void k_conv(const float* __restrict__ W_ih, const float* __restrict__ W_out) {
    int i4 = blockIdx.x * 256 + threadIdx.x;
    const int NIH = G4 * HH / 4;          // 262144 float4s
    if (i4 < NIH) {
        float4 v = *(const float4*)&W_ih[(size_t)i4 * 4];
        uint2 h, l; split4(v, h, l);
        *(uint2*)&g_Wih_h[(size_t)i4 * 4] = h;
        *(uint2*)&g_Wih_l[(size_t)i4 * 4] = l;
    } else {
        size_t j = (size_t)(i4 - NIH);    // < 4,096,000
        float4 v = *(const float4*)&W_out[j * 4];
        uint2 h, l; split4(v, h, l);
        *(uint2*)&g_Wout_h[j * 4] = h;
        *(uint2*)&g_Wout_l[j * 4] = l;
    }
}

// ---------------- kernel 4: pipelined bf16x3 mma.sync GEMM ----------------
// C[n][m] = dot(A[n,:], B[m,:]) + bias[m], K = 512.
// A = (Ah, Al) [Nrows x 512] bf16 K-major; B = (Bh, Bl) [M x 512].
// Tile 128(n) x 128(m), BK = 64 bf16 (128B rows, sw128-swizzled smem),
// 3-stage cp.async pipeline, 8 warps; warp computes 64x32 via 4x4 m16n8k16,
// 3 mma per fragment pair: AhBh + AhBl + AlBh (fp32 accum throughout).
#define KC 64
#define OP_BYTES 16384                  // 128 rows * 128 B
#define ST_AH 0
#define ST_AL 16384
#define ST_BH 32768
#define ST_BL 49152
#define STAGE_BYTES 65536
#define NSTAGE 3
#define GSMEM (NSTAGE * STAGE_BYTES)    // 192 KB

__global__ void __launch_bounds__(256, 1) gemm_tc(
    const __nv_bfloat16* __restrict__ Ah, const __nv_bfloat16* __restrict__ Al,
    const __nv_bfloat16* __restrict__ Bh, const __nv_bfloat16* __restrict__ Bl,
    const float* __restrict__ bias, float* __restrict__ C, int M)
{
    extern __shared__ char smem[];
    const uint32_t sb = smem_u32(smem);
    const int tid  = threadIdx.x;
    const int lane = tid & 31, wid = tid >> 5;
    const int warp_n = wid >> 2;          // 0..1 -> 64-row slab (A rows)
    const int warp_m = wid & 3;           // 0..3 -> 32-row slab (B rows)
    const int n0 = blockIdx.y * 128;
    const int m0 = blockIdx.x * 128;

    float c[4][4][4];
#pragma unroll
    for (int i = 0; i < 4; i++)
#pragma unroll
        for (int j = 0; j < 4; j++)
#pragma unroll
            for (int q = 0; q < 4; q++) c[i][j][q] = 0.0f;

    // per-lane ldmatrix source coordinates (identical to round-2 passing code)
    const int a_lr = lane & 7, a_sel = lane >> 3;
    const int a_row = (a_sel & 1) * 8 + a_lr;     // within 16-row tile
    const int a_col = (a_sel >> 1) * 8;           // 0 or 8
    const int b_l   = lane & 15;
    const int b_row = b_l & 7;                    // within 8-row tile
    const int b_col = (b_l >> 3) * 8;             // 0 or 8

    // ---- async chunk loader: 16 cp.async(16B) per thread per chunk ----
    auto load_chunk = [&](int cc) {
        const uint32_t sbase = sb + (uint32_t)(cc % NSTAGE) * STAGE_BYTES;
        const int kb = cc * KC;
#pragma unroll
        for (int i = 0; i < 4; i++) {
            int idx = tid + i * 256;               // 0..1023
            int row = idx >> 3, seg = idx & 7;     // 128 rows x 8 16B-segs
            uint32_t sw = sw128((uint32_t)(row * 128 + seg * 16));
            size_t goa = (size_t)(n0 + row) * HH + kb + seg * 8;
            size_t gob = (size_t)(m0 + row) * HH + kb + seg * 8;
            cpasync16(sbase + ST_AH + sw, Ah + goa);
            cpasync16(sbase + ST_AL + sw, Al + goa);
            cpasync16(sbase + ST_BH + sw, Bh + gob);
            cpasync16(sbase + ST_BL + sw, Bl + gob);
        }
        cp_commit();
    };

    load_chunk(0);
    load_chunk(1);
    load_chunk(2);

#pragma unroll 1
    for (int cc = 0; cc < 8; cc++) {
        if (cc < 6)      cp_wait<2>();
        else if (cc == 6) cp_wait<1>();
        else              cp_wait<0>();
        __syncthreads();
        const uint32_t sbase = sb + (uint32_t)(cc % NSTAGE) * STAGE_BYTES;

#pragma unroll
        for (int kk = 0; kk < KC; kk += 16) {
            uint32_t ah[4][4], al[4][4], bh[4][2], bl[4][2];
#pragma unroll
            for (int i = 0; i < 4; i++) {
                int r = warp_n * 64 + i * 16 + a_row;
                uint32_t sw = sw128((uint32_t)(r * 128 + (kk + a_col) * 2));
                ldsm4(ah[i], sbase + ST_AH + sw);
                ldsm4(al[i], sbase + ST_AL + sw);
            }
#pragma unroll
            for (int j = 0; j < 4; j++) {
                int r = warp_m * 32 + j * 8 + b_row;
                uint32_t sw = sw128((uint32_t)(r * 128 + (kk + b_col) * 2));
                ldsm2(bh[j], sbase + ST_BH + sw);
                ldsm2(bl[j], sbase + ST_BL + sw);
            }
#pragma unroll
            for (int i = 0; i < 4; i++)
#pragma unroll
                for (int j = 0; j < 4; j++) {
                    mma16816(c[i][j], ah[i], bh[j]);
                    mma16816(c[i][j], ah[i], bl[j]);
                    mma16816(c[i][j], al[i], bh[j]);
                }
        }
        __syncthreads();                 // all warps done reading this stage
        if (cc < 5) load_chunk(cc + 3);  // refill freed stage
    }

    // ---- epilogue: add bias, store f32 (round-2 passing code) ----------
#pragma unroll
    for (int i = 0; i < 4; i++) {
        int n = n0 + warp_n * 64 + i * 16 + (lane >> 2);
#pragma unroll
        for (int j = 0; j < 4; j++) {
            int m = m0 + warp_m * 32 + j * 8 + ((lane & 3) << 1);
            float bx = bias[m], by = bias[m + 1];
            *(float2*)&C[(size_t)n * M + m]       = make_float2(c[i][j][0] + bx, c[i][j][1] + by);
            *(float2*)&C[(size_t)(n + 8) * M + m] = make_float2(c[i][j][2] + bx, c[i][j][3] + by);
        }
    }
}

// ---------------- kernel 5: persistent LSTM -------------------------------
// 128 CTAs x 128 threads, grid co-resident (128 <= 148 SMs) -> safe barrier.
__global__ void __launch_bounds__(128) k_lstm(const float* __restrict__ enc_h,
                                              const float* __restrict__ enc_c,
                                              const float* __restrict__ W_hh) {
    extern __shared__ float sm[];
    float* w_sh    = sm;                 // [16][516]
    float* h_sh    = sm + 16 * 516;      // [16][516]  (b-major)
    float* c_sh    = sm + 32 * 516;      // [4][16]    (jj, b)
    float* gate_sh = c_sh + 64;          // [16][16]   (rl = gate*4+jj, b)

    const int cb  = blockIdx.x;
    const int tid = threadIdx.x;

    for (int f = tid; f < 2048; f += 128) {
        int rl = f >> 7, k4 = (f & 127) << 2;
        int grow = (rl >> 2) * HH + cb * 4 + (rl & 3);
        *(float4*)&w_sh[rl * 516 + k4] = *(const float4*)&W_hh[(size_t)grow * HH + k4];
    }
    if (tid < 64) {
        int jj = tid >> 4, b = tid & 15;
        c_sh[jj * 16 + b] = enc_c[b * HH + cb * 4 + jj];
    }
    __syncthreads();

    const int rp = tid >> 4;
    const int b  = tid & 15;
    const int r0 = rp * 2, r1 = r0 + 1;
    const int g0 = r0 >> 2, j0 = r0 & 3;
    const int g1 = r1 >> 2, j1 = r1 & 3;

    for (int t = 0; t < TT; t++) {
        const float* hsrc = (t == 0) ? enc_h : &g_Hs[(size_t)(t - 1) * BB * HH];
        for (int f = tid; f < 2048; f += 128) {
            int bb = f >> 7, k4 = (f & 127) << 2;
            *(float4*)&h_sh[bb * 516 + k4] = *(const float4*)&hsrc[bb * HH + k4];
        }
        __syncthreads();

        float acc0 = g_Xg[(size_t)(t * BB + b) * G4 + g0 * HH + cb * 4 + j0];
        float acc1 = g_Xg[(size_t)(t * BB + b) * G4 + g1 * HH + cb * 4 + j1];
        const float* hp = &h_sh[b * 516];
        const float* w0 = &w_sh[r0 * 516];
        const float* w1 = &w_sh[r1 * 516];
#pragma unroll 8
        for (int k = 0; k < HH; k += 4) {
            float4 hv = *(const float4*)&hp[k];
            float4 wa = *(const float4*)&w0[k];
            float4 wb = *(const float4*)&w1[k];
            acc0 += hv.x * wa.x + hv.y * wa.y + hv.z * wa.z + hv.w * wa.w;
            acc1 += hv.x * wb.x + hv.y * wb.y + hv.z * wb.z + hv.w * wb.w;
        }
        gate_sh[r0 * 16 + b] = acc0;
        gate_sh[r1 * 16 + b] = acc1;
        __syncthreads();

        if (tid < 64) {
            int jj = tid >> 4, bb = tid & 15;
            float iv = sigm (gate_sh[(0 * 4 + jj) * 16 + bb]);
            float fv = sigm (gate_sh[(1 * 4 + jj) * 16 + bb]);
            float gv = tanhf(gate_sh[(2 * 4 + jj) * 16 + bb]);
            float ov = sigm (gate_sh[(3 * 4 + jj) * 16 + bb]);
            float cc = fv * c_sh[jj * 16 + bb] + iv * gv;
            c_sh[jj * 16 + bb] = cc;
            float hv = ov * tanhf(cc);
            int hidx = (t * BB + bb) * HH + cb * 4 + jj;
            g_Hs[hidx] = hv;
            __nv_bfloat16 hb = __float2bfloat16(hv);
            g_Hh[hidx] = hb;
            g_Hl[hidx] = __float2bfloat16(hv - __bfloat162float(hb));
        }
        __threadfence();
        __syncthreads();
        if (tid == 0) {
            atomicAdd(&g_bar[t], 1u);
            while (((volatile unsigned*)g_bar)[t] < (unsigned)gridDim.x) __nanosleep(64);
            __threadfence();
        }
        __syncthreads();
    }
}

// ---------------- launcher -------------------------------------------------
extern "C" void kernel_launch(void* const* d_in, const int* in_sizes, int n_in,
                              void* d_out, int out_size) {
    const int*   xs    = (const int*)  d_in[0];
    // d_in[1] = xs_len (unused by reference semantics)
    const float* enc_h = (const float*)d_in[2];
    const float* enc_c = (const float*)d_in[3];
    const float* emb   = (const float*)d_in[4];
    const float* W_ih  = (const float*)d_in[5];
    const float* W_hh  = (const float*)d_in[6];
    const float* b_ih  = (const float*)d_in[7];
    const float* b_hh  = (const float*)d_in[8];
    const float* W_out = (const float*)d_in[9];
    const float* b_out = (const float*)d_in[10];
    float* out = (float*)d_out;

    __nv_bfloat16 *pXh, *pXl, *pWih_h, *pWih_l, *pWout_h, *pWout_l, *pHh, *pHl;
    float *pXg, *pbias;
    cudaGetSymbolAddress((void**)&pXh,     g_Xh);
    cudaGetSymbolAddress((void**)&pXl,     g_Xl);
    cudaGetSymbolAddress((void**)&pWih_h,  g_Wih_h);
    cudaGetSymbolAddress((void**)&pWih_l,  g_Wih_l);
    cudaGetSymbolAddress((void**)&pWout_h, g_Wout_h);
    cudaGetSymbolAddress((void**)&pWout_l, g_Wout_l);
    cudaGetSymbolAddress((void**)&pHh,     g_Hh);
    cudaGetSymbolAddress((void**)&pHl,     g_Hl);
    cudaGetSymbolAddress((void**)&pXg,     g_Xg);
    cudaGetSymbolAddress((void**)&pbias,   g_bias);

    k_gather<<<1024, 256>>>(xs, emb);
    k_prep<<<8, 256>>>(b_ih, b_hh);
    k_conv<<<(G4*HH/4 + (int)((size_t)VV*HH/4)) / 256, 256>>>(W_ih, W_out);

    cudaFuncSetAttribute(gemm_tc, cudaFuncAttributeMaxDynamicSharedMemorySize, GSMEM);

    // Xg = X @ W_ih^T + (b_ih + b_hh)   [2048 x 2048]
    gemm_tc<<<dim3(G4 / 128, (TT * BB) / 128), 256, GSMEM>>>(
        pXh, pXl, pWih_h, pWih_l, pbias, pXg, G4);

    int lsmem = (2 * 16 * 516 + 64 + 256) * (int)sizeof(float);  // ~67 KB
    cudaFuncSetAttribute(k_lstm, cudaFuncAttributeMaxDynamicSharedMemorySize, lsmem);
    k_lstm<<<128, 128, lsmem>>>(enc_h, enc_c, W_hh);

    // logits = Hs @ W_out^T + b_out     [2048 x 32000]
    gemm_tc<<<dim3(VV / 128, (TT * BB) / 128), 256, GSMEM>>>(
        pHh, pHl, pWout_h, pWout_l, b_out, out, VV);
}